// round 6
// baseline (speedup 1.0000x reference)
#include <cuda_runtime.h>
#include <cstdint>

#define BATCH 4
#define NTOK 4096        // H*W
#define CDIM 64
#define DDIM 8
#define KT 32            // keys per tile
#define NT (NTOK / KT)   // 128 tiles
#define QB 128           // queries per CTA

typedef unsigned long long u64;
typedef unsigned int u32;

#define FMA2(d, a, b, c) \
    asm("fma.rn.f32x2 %0, %1, %2, %3;" : "=l"(d) : "l"(a), "l"(b), "l"(c))
#define MUL2(d, a, b) \
    asm("mul.rn.f32x2 %0, %1, %2;" : "=l"(d) : "l"(a), "l"(b))
#define UNPACK2(lo, hi, s) \
    asm("mov.b64 {%0, %1}, %2;" : "=f"(lo), "=f"(hi) : "l"(s))

// group barrier: 256 threads, barrier id 1 or 2
#define GBAR(id) asm volatile("bar.sync %0, %1;" :: "r"(id), "r"(256) : "memory")

__device__ __forceinline__ u32 tf32_bits(float x) {
    u32 r;
    asm("cvt.rna.tf32.f32 %0, %1;" : "=r"(r) : "f"(x));
    return r;
}

// D(16x8,f32) += A(16x8,tf32) * B(8x8,tf32)
__device__ __forceinline__ void mma_tf32(float* d,
                                         u32 a0, u32 a1, u32 a2, u32 a3,
                                         u32 b0, u32 b1) {
    asm("mma.sync.aligned.m16n8k8.row.col.f32.tf32.tf32.f32 "
        "{%0,%1,%2,%3}, {%4,%5,%6,%7}, {%8,%9}, {%0,%1,%2,%3};"
        : "+f"(d[0]), "+f"(d[1]), "+f"(d[2]), "+f"(d[3])
        : "r"(a0), "r"(a1), "r"(a2), "r"(a3), "r"(b0), "r"(b1));
}

// ---------------- scratch ----------------
__device__ float g_q[BATCH * NTOK * DDIM];
__device__ float g_k[BATCH * NTOK * DDIM];
// channel-major V, tf32-rounded, token order PERMUTED within each 32-block:
// key' = (key>>2) | ((key&3)<<3)  — so mma B-fragments are contiguous float4s
__device__ float g_vt[(size_t)BATCH * CDIM * NTOK];

// ---------------------------------------------------------------------------
// Projection: q = x@Wf+bf, k = x@Wg+bg, v^T = (x@Wh+bh)^T (tf32, permuted)
// 128 threads/CTA, one row per thread, x read straight from gmem (L2).
// ---------------------------------------------------------------------------
__global__ __launch_bounds__(128) void proj_kernel(
    const float* __restrict__ x,
    const float* __restrict__ Wf, const float* __restrict__ bf,
    const float* __restrict__ Wg, const float* __restrict__ bg,
    const float* __restrict__ Wh, const float* __restrict__ bh)
{
    __shared__ __align__(16) float WhT[64][68];
    __shared__ float bias[CDIM];

    const int tid = threadIdx.x;
    const int row = blockIdx.x * 128 + tid;

    for (int i = tid; i < 64 * 64; i += 128)
        WhT[i & 63][i >> 6] = Wh[i];
    if (tid < 64) bias[tid] = bh[tid];
    __syncthreads();

    float xr[64];
    const float4* xrow = (const float4*)(x + (size_t)row * CDIM);
#pragma unroll
    for (int c4 = 0; c4 < 16; c4++) {
        const float4 t = __ldg(&xrow[c4]);
        xr[c4 * 4 + 0] = t.x; xr[c4 * 4 + 1] = t.y;
        xr[c4 * 4 + 2] = t.z; xr[c4 * 4 + 3] = t.w;
    }

    const int b  = row >> 12;
    const int nl = row & (NTOK - 1);
    const int key  = nl & 31;
    const int nlp  = (nl & ~31) | ((key >> 2) | ((key & 3) << 3));

#pragma unroll 1
    for (int ch = 0; ch < CDIM; ch++) {
        float a = bias[ch];
        const float4* w = (const float4*)&WhT[ch][0];
#pragma unroll
        for (int c4 = 0; c4 < 16; c4++) {
            const float4 ww = w[c4];
            a += xr[c4 * 4 + 0] * ww.x;
            a += xr[c4 * 4 + 1] * ww.y;
            a += xr[c4 * 4 + 2] * ww.z;
            a += xr[c4 * 4 + 3] * ww.w;
        }
        g_vt[((size_t)b * CDIM + ch) * NTOK + nlp] = __uint_as_float(tf32_bits(a));
    }

#pragma unroll 1
    for (int ch = 0; ch < DDIM; ch++) {
        float aq = bf[ch];
        float ak = bg[ch];
#pragma unroll
        for (int c = 0; c < CDIM; c++) {
            aq += xr[c] * Wf[c * DDIM + ch];
            ak += xr[c] * Wg[c * DDIM + ch];
        }
        g_q[row * DDIM + ch] = aq;
        g_k[row * DDIM + ch] = ak;
    }
}

// ---------------------------------------------------------------------------
// Attention, split-K in-CTA: 512 threads = 2 groups of 256, named barriers.
// o and l linear in tiles (exp never overflows) -> merge partials at end.
// B-fragments of V read as float4 thanks to the key permutation.
// ---------------------------------------------------------------------------
__global__ __launch_bounds__(512, 1) void attn_kernel(
    const float* __restrict__ x,
    const float* __restrict__ gamma_p,
    float* __restrict__ out)
{
    __shared__ __align__(16) float Ks[2][KT * DDIM];   // 2 x 1 KB
    __shared__ __align__(16) float Vs[2][CDIM][36];    // 2 x 9 KB (permuted keys)
    __shared__ __align__(16) float osm[QB][34];        // 17 KB
    __shared__ float lsm[QB];

    const int tid  = threadIdx.x;
    const int grp  = tid >> 8;
    const int lt   = tid & 255;
    const int warp = lt >> 5;
    const int lane = tid & 31;
    const int g    = lane >> 2;
    const int tig  = lane & 3;
    const int bid  = blockIdx.y;
    const int q0   = blockIdx.x * QB;
    const int barid = grp + 1;

    const int rA_l = warp * 16 + g;
    const int rB_l = rA_l + 8;
    const int rowA = q0 + rA_l;
    const int rowB = q0 + rB_l;

    u64 qa[4], qb[4];
    {
        const u64* pA = (const u64*)(g_q + ((size_t)bid * NTOK + rowA) * DDIM);
        const u64* pB = (const u64*)(g_q + ((size_t)bid * NTOK + rowB) * DDIM);
#pragma unroll
        for (int i = 0; i < 4; i++) { qa[i] = pA[i]; qb[i] = pB[i]; }
    }

    float o[8][4];
#pragma unroll
    for (int n = 0; n < 8; n++)
#pragma unroll
        for (int r = 0; r < 4; r++) o[n][r] = 0.0f;
    float la0 = 0.0f, la1 = 0.0f, lb0 = 0.0f, lb1 = 0.0f;

    const float* kbase = g_k + (size_t)bid * NTOK * DDIM;
    const float* vbase = g_vt + (size_t)bid * CDIM * NTOK;

    const int t0 = grp * (NT / 2);
    const int t1 = t0 + (NT / 2);

    float4 kpre, vpre0, vpre1;
    const int vch  = lt >> 3;         // 0..31
    const int vpos = (lt & 7) * 4;    // permuted key offset 0..28

    {
        const int k0 = t0 * KT;
        if (lt < 64) kpre = ((const float4*)(kbase + (size_t)k0 * DDIM))[lt];
        vpre0 = *(const float4*)(vbase + (size_t)vch * NTOK + k0 + vpos);
        vpre1 = *(const float4*)(vbase + (size_t)(vch + 32) * NTOK + k0 + vpos);
        if (lt < 64) ((float4*)Ks[grp])[lt] = kpre;
        *(float4*)&Vs[grp][vch][vpos]      = vpre0;
        *(float4*)&Vs[grp][vch + 32][vpos] = vpre1;
    }
    GBAR(barid);

    for (int t = t0; t < t1; t++) {
        const bool more = (t + 1 < t1);
        if (more) {
            const int k0 = (t + 1) * KT;
            if (lt < 64) kpre = ((const float4*)(kbase + (size_t)k0 * DDIM))[lt];
            vpre0 = *(const float4*)(vbase + (size_t)vch * NTOK + k0 + vpos);
            vpre1 = *(const float4*)(vbase + (size_t)(vch + 32) * NTOK + k0 + vpos);
        }

        // ---- scalar QK + exp into A-fragment layout ----
        u32 pa[8], pb[8];
        const float* kr = Ks[grp];
#pragma unroll
        for (int u = 0; u < 8; u++) {
            const int j = tig + 4 * u;
            const ulonglong2 kl = *(const ulonglong2*)&kr[j * DDIM];
            const ulonglong2 kh = *(const ulonglong2*)&kr[j * DDIM + 4];
            u64 d;
            float lo, hi;
            MUL2(d, qa[0], kl.x);
            FMA2(d, qa[1], kl.y, d);
            FMA2(d, qa[2], kh.x, d);
            FMA2(d, qa[3], kh.y, d);
            UNPACK2(lo, hi, d);
            const u32 ra = tf32_bits(__expf(lo + hi));
            pa[u] = ra;
            if (u & 1) la1 += __uint_as_float(ra); else la0 += __uint_as_float(ra);

            MUL2(d, qb[0], kl.x);
            FMA2(d, qb[1], kl.y, d);
            FMA2(d, qb[2], kh.x, d);
            FMA2(d, qb[3], kh.y, d);
            UNPACK2(lo, hi, d);
            const u32 rb = tf32_bits(__expf(lo + hi));
            pb[u] = rb;
            if (u & 1) lb1 += __uint_as_float(rb); else lb0 += __uint_as_float(rb);
        }

        // ---- P x V via mma.sync; B-fragments as two float4 per n ----
#pragma unroll
        for (int n = 0; n < 8; n++) {
            const float4 vA = *(const float4*)&Vs[grp][n * 8 + g][8 * tig];
            const float4 vB = *(const float4*)&Vs[grp][n * 8 + g][8 * tig + 4];
            mma_tf32(o[n], pa[0], pb[0], pa[1], pb[1],
                     __float_as_uint(vA.x), __float_as_uint(vA.y));
            mma_tf32(o[n], pa[2], pb[2], pa[3], pb[3],
                     __float_as_uint(vA.z), __float_as_uint(vA.w));
            mma_tf32(o[n], pa[4], pb[4], pa[5], pb[5],
                     __float_as_uint(vB.x), __float_as_uint(vB.y));
            mma_tf32(o[n], pa[6], pb[6], pa[7], pb[7],
                     __float_as_uint(vB.z), __float_as_uint(vB.w));
        }

        GBAR(barid);
        if (more) {
            if (lt < 64) ((float4*)Ks[grp])[lt] = kpre;
            *(float4*)&Vs[grp][vch][vpos]      = vpre0;
            *(float4*)&Vs[grp][vch + 32][vpos] = vpre1;
        }
        GBAR(barid);
    }

    float la = la0 + la1;
    float lb = lb0 + lb1;
    la += __shfl_xor_sync(0xffffffffu, la, 1);
    la += __shfl_xor_sync(0xffffffffu, la, 2);
    lb += __shfl_xor_sync(0xffffffffu, lb, 1);
    lb += __shfl_xor_sync(0xffffffffu, lb, 2);

    // ---- merge group partials ----
#pragma unroll
    for (int h = 0; h < 2; h++) {
        if (grp == 1) {
            if (h == 0 && tig == 0) {
                lsm[rA_l] = la;
                lsm[rB_l] = lb;
            }
#pragma unroll
            for (int n = h * 4; n < h * 4 + 4; n++) {
                const int col = (n * 8 + 2 * tig) & 31;
                *(float2*)&osm[rA_l][col] = make_float2(o[n][0], o[n][1]);
                *(float2*)&osm[rB_l][col] = make_float2(o[n][2], o[n][3]);
            }
        }
        __syncthreads();
        if (grp == 0) {
            if (h == 0) { la += lsm[rA_l]; lb += lsm[rB_l]; }
#pragma unroll
            for (int n = h * 4; n < h * 4 + 4; n++) {
                const int col = (n * 8 + 2 * tig) & 31;
                const float2 ea = *(const float2*)&osm[rA_l][col];
                const float2 eb = *(const float2*)&osm[rB_l][col];
                o[n][0] += ea.x; o[n][1] += ea.y;
                o[n][2] += eb.x; o[n][3] += eb.y;
            }
        }
        __syncthreads();
    }

    if (grp == 0) {
        const float gamma = *gamma_p;
        const float gia = gamma / la;
        const float gib = gamma / lb;
        const size_t baseA = ((size_t)bid * NTOK + rowA) * CDIM;
        const size_t baseB = ((size_t)bid * NTOK + rowB) * CDIM;
#pragma unroll
        for (int n = 0; n < 8; n++) {
            const int col = n * 8 + 2 * tig;
            float2 xvA = *(const float2*)&x[baseA + col];
            float2 xvB = *(const float2*)&x[baseB + col];
            float2 ovA, ovB;
            ovA.x = gia * o[n][0] + xvA.x;
            ovA.y = gia * o[n][1] + xvA.y;
            ovB.x = gib * o[n][2] + xvB.x;
            ovB.y = gib * o[n][3] + xvB.y;
            *(float2*)&out[baseA + col] = ovA;
            *(float2*)&out[baseB + col] = ovB;
        }
    }
}

extern "C" void kernel_launch(void* const* d_in, const int* in_sizes, int n_in,
                              void* d_out, int out_size)
{
    const float* x     = (const float*)d_in[0];
    const float* Wf    = (const float*)d_in[1];
    const float* bf    = (const float*)d_in[2];
    const float* Wg    = (const float*)d_in[3];
    const float* bg    = (const float*)d_in[4];
    const float* Wh    = (const float*)d_in[5];
    const float* bh    = (const float*)d_in[6];
    const float* gamma = (const float*)d_in[7];
    float* out = (float*)d_out;

    proj_kernel<<<(BATCH * NTOK) / 128, 128>>>(x, Wf, bf, Wg, bg, Wh, bh);
    attn_kernel<<<dim3(NTOK / QB, BATCH), 512>>>(x, gamma, out);
}

// round 7
// speedup vs baseline: 1.5574x; 1.5574x over previous
#include <cuda_runtime.h>
#include <cstdint>

#define BATCH 4
#define NTOK 4096        // H*W
#define CDIM 64
#define DDIM 8
#define KT 32            // keys per tile
#define NT (NTOK / KT)   // 128 tiles
#define QB 128           // queries per CTA

typedef unsigned int u32;

// group barrier: 256 threads, barrier id 1 or 2
#define GBAR(id) asm volatile("bar.sync %0, %1;" :: "r"(id), "r"(256) : "memory")

__device__ __forceinline__ u32 tf32_bits(float x) {
    u32 r;
    asm("cvt.rna.tf32.f32 %0, %1;" : "=r"(r) : "f"(x));
    return r;
}
__device__ __forceinline__ float tf32f(float x) {
    return __uint_as_float(tf32_bits(x));
}

// D(16x8,f32) += A(16x8,tf32) * B(8x8,tf32)
__device__ __forceinline__ void mma_tf32(float* d,
                                         u32 a0, u32 a1, u32 a2, u32 a3,
                                         u32 b0, u32 b1) {
    asm("mma.sync.aligned.m16n8k8.row.col.f32.tf32.tf32.f32 "
        "{%0,%1,%2,%3}, {%4,%5,%6,%7}, {%8,%9}, {%0,%1,%2,%3};"
        : "+f"(d[0]), "+f"(d[1]), "+f"(d[2]), "+f"(d[3])
        : "r"(a0), "r"(a1), "r"(a2), "r"(a3), "r"(b0), "r"(b1));
}

// ---------------- scratch ----------------
__device__ float g_q[BATCH * NTOK * DDIM];                 // fp32 q
__device__ float g_kb[BATCH * NTOK * DDIM];                // tf32(k), dims permuted [0,4,1,5,2,6,3,7]
__device__ float g_kd[BATCH * NTOK * DDIM];                // tf32(k - kb), same layout
__device__ float g_vt[(size_t)BATCH * CDIM * NTOK];        // tf32 v, channel-major,
// key order permuted within each 32-block: key k stored at position
// psi(k) = 8*((k>>1)&3) + 2*(k>>3) + (k&1)

// ---------------------------------------------------------------------------
// Projection. 128 threads, 64 rows/CTA (2 threads per row: channel halves).
// x staged coalesced into smem; Wh transposed in smem; Wf/Wg transposed.
// ---------------------------------------------------------------------------
__global__ __launch_bounds__(128) void proj_kernel(
    const float* __restrict__ x,
    const float* __restrict__ Wf, const float* __restrict__ bf,
    const float* __restrict__ Wg, const float* __restrict__ bg,
    const float* __restrict__ Wh, const float* __restrict__ bh)
{
    __shared__ __align__(16) float xs[64][68];
    __shared__ __align__(16) float WhT[64][68];
    __shared__ __align__(16) float WfT[8][68];
    __shared__ __align__(16) float WgT[8][68];
    __shared__ float bias[64];

    const int tid = threadIdx.x;
    const int rowbase = blockIdx.x * 64;

    for (int i = tid; i < 1024; i += 128) {
        const int r = i >> 4, c4 = i & 15;
        *(float4*)&xs[r][c4 * 4] = ((const float4*)(x + (size_t)rowbase * CDIM))[i];
    }
    for (int i = tid; i < 4096; i += 128)
        WhT[i & 63][i >> 6] = Wh[i];
    for (int i = tid; i < 512; i += 128) {
        WfT[i & 7][i >> 3] = Wf[i];
        WgT[i & 7][i >> 3] = Wg[i];
    }
    if (tid < 64) bias[tid] = bh[tid];
    __syncthreads();

    const int rloc = (tid & 31) | ((tid >> 6) << 5);   // 0..63
    const int half = (tid >> 5) & 1;
    const int row  = rowbase + rloc;
    const int b    = row >> 12;
    const int nl   = row & (NTOK - 1);
    const int key  = nl & 31;
    const int vp   = 8 * ((key >> 1) & 3) + 2 * (key >> 3) + (key & 1);  // psi(key)
    const int nlp  = (nl & ~31) | vp;

    float xr[64];
#pragma unroll
    for (int c4 = 0; c4 < 16; c4++) {
        const float4 t = *(const float4*)&xs[rloc][c4 * 4];
        xr[c4 * 4 + 0] = t.x; xr[c4 * 4 + 1] = t.y;
        xr[c4 * 4 + 2] = t.z; xr[c4 * 4 + 3] = t.w;
    }

    // v: my 32-channel half (tf32-rounded, channel-major, key-permuted)
#pragma unroll 1
    for (int ch = half * 32; ch < half * 32 + 32; ch++) {
        float a = bias[ch];
        const float4* w = (const float4*)&WhT[ch][0];
#pragma unroll
        for (int c4 = 0; c4 < 16; c4++) {
            const float4 ww = w[c4];
            a += xr[c4 * 4 + 0] * ww.x;
            a += xr[c4 * 4 + 1] * ww.y;
            a += xr[c4 * 4 + 2] * ww.z;
            a += xr[c4 * 4 + 3] * ww.w;
        }
        g_vt[((size_t)b * CDIM + ch) * NTOK + nlp] = tf32f(a);
    }

    if (half == 0) {
        // q (fp32, plain layout)
        float q8[8];
#pragma unroll
        for (int ch = 0; ch < DDIM; ch++) {
            float a = __ldg(&bf[ch]);
            const float4* w = (const float4*)&WfT[ch][0];
#pragma unroll
            for (int c4 = 0; c4 < 16; c4++) {
                const float4 ww = w[c4];
                a += xr[c4 * 4 + 0] * ww.x;
                a += xr[c4 * 4 + 1] * ww.y;
                a += xr[c4 * 4 + 2] * ww.z;
                a += xr[c4 * 4 + 3] * ww.w;
            }
            q8[ch] = a;
        }
        float* qdst = g_q + (size_t)row * DDIM;
        *(float4*)qdst       = make_float4(q8[0], q8[1], q8[2], q8[3]);
        *(float4*)(qdst + 4) = make_float4(q8[4], q8[5], q8[6], q8[7]);
    } else {
        // k: split into tf32 big + residual, dims permuted [0,4,1,5,2,6,3,7]
        float kb8[8], kd8[8];
#pragma unroll
        for (int ch = 0; ch < DDIM; ch++) {
            float a = __ldg(&bg[ch]);
            const float4* w = (const float4*)&WgT[ch][0];
#pragma unroll
            for (int c4 = 0; c4 < 16; c4++) {
                const float4 ww = w[c4];
                a += xr[c4 * 4 + 0] * ww.x;
                a += xr[c4 * 4 + 1] * ww.y;
                a += xr[c4 * 4 + 2] * ww.z;
                a += xr[c4 * 4 + 3] * ww.w;
            }
            const int pos = (ch < 4) ? 2 * ch : 2 * (ch - 4) + 1;
            const float big = tf32f(a);
            kb8[pos] = big;
            kd8[pos] = tf32f(a - big);
        }
        float* kbd = g_kb + (size_t)row * DDIM;
        float* kdd = g_kd + (size_t)row * DDIM;
        *(float4*)kbd       = make_float4(kb8[0], kb8[1], kb8[2], kb8[3]);
        *(float4*)(kbd + 4) = make_float4(kb8[4], kb8[5], kb8[6], kb8[7]);
        *(float4*)kdd       = make_float4(kd8[0], kd8[1], kd8[2], kd8[3]);
        *(float4*)(kdd + 4) = make_float4(kd8[4], kd8[5], kd8[6], kd8[7]);
    }
}

// ---------------------------------------------------------------------------
// Attention: QK via 3xTF32 mma.sync (fp32-accurate S), exp in registers whose
// layout IS the PV A-fragment (via the psi key permutation), PV via tf32 mma.
// 512 threads = 2 split-K groups of 256 (named barriers), o/l linear (exp
// never overflows), partials merged through smem at the end.
// ---------------------------------------------------------------------------
__global__ __launch_bounds__(512, 1) void attn_kernel(
    const float* __restrict__ x,
    const float* __restrict__ gamma_p,
    float* __restrict__ out)
{
    __shared__ __align__(16) float Kb[2][KT][DDIM];   // 2 KB
    __shared__ __align__(16) float Kd[2][KT][DDIM];   // 2 KB
    __shared__ __align__(16) float Vs[2][CDIM][36];   // 18 KB
    __shared__ __align__(16) float osm[QB][34];       // 17 KB
    __shared__ float lsm[QB];

    const int tid  = threadIdx.x;
    const int grp  = tid >> 8;
    const int lt   = tid & 255;
    const int warp = lt >> 5;
    const int lane = tid & 31;
    const int g    = lane >> 2;
    const int tig  = lane & 3;
    const int bid  = blockIdx.y;
    const int q0   = blockIdx.x * QB;
    const int barid = grp + 1;

    const int rA_l = warp * 16 + g;
    const int rB_l = rA_l + 8;
    const int rowA = q0 + rA_l;
    const int rowB = q0 + rB_l;

    // Q A-fragments, 3xTF32 split: a0=(rowA,tig) a1=(rowB,tig) a2=(rowA,tig+4) a3=(rowB,tig+4)
    u32 Qb[4], Qd[4];
    {
        const float* qA = g_q + ((size_t)bid * NTOK + rowA) * DDIM;
        const float* qB = g_q + ((size_t)bid * NTOK + rowB) * DDIM;
        const float qv[4] = { qA[tig], qB[tig], qA[tig + 4], qB[tig + 4] };
#pragma unroll
        for (int i = 0; i < 4; i++) {
            Qb[i] = tf32_bits(qv[i]);
            Qd[i] = tf32_bits(qv[i] - __uint_as_float(Qb[i]));
        }
    }

    float o[8][4];
#pragma unroll
    for (int n = 0; n < 8; n++)
#pragma unroll
        for (int r = 0; r < 4; r++) o[n][r] = 0.0f;
    float la0 = 0.0f, la1 = 0.0f, lb0 = 0.0f, lb1 = 0.0f;

    const float* kbbase = g_kb + (size_t)bid * NTOK * DDIM;
    const float* kdbase = g_kd + (size_t)bid * NTOK * DDIM;
    const float* vbase  = g_vt + (size_t)bid * CDIM * NTOK;

    const int t0 = grp * (NT / 2);
    const int t1 = t0 + (NT / 2);

    float4 kbp, kdp, vpre0, vpre1;
    const int vch  = lt >> 3;
    const int vpos = (lt & 7) * 4;

    {
        const int k0 = t0 * KT;
        if (lt < 64) {
            kbp = ((const float4*)(kbbase + (size_t)k0 * DDIM))[lt];
            kdp = ((const float4*)(kdbase + (size_t)k0 * DDIM))[lt];
        }
        vpre0 = *(const float4*)(vbase + (size_t)vch * NTOK + k0 + vpos);
        vpre1 = *(const float4*)(vbase + (size_t)(vch + 32) * NTOK + k0 + vpos);
        if (lt < 64) {
            ((float4*)Kb[grp])[lt] = kbp;
            ((float4*)Kd[grp])[lt] = kdp;
        }
        *(float4*)&Vs[grp][vch][vpos]      = vpre0;
        *(float4*)&Vs[grp][vch + 32][vpos] = vpre1;
    }
    GBAR(barid);

    for (int t = t0; t < t1; t++) {
        const bool more = (t + 1 < t1);
        if (more) {
            const int k0 = (t + 1) * KT;
            if (lt < 64) {
                kbp = ((const float4*)(kbbase + (size_t)k0 * DDIM))[lt];
                kdp = ((const float4*)(kdbase + (size_t)k0 * DDIM))[lt];
            }
            vpre0 = *(const float4*)(vbase + (size_t)vch * NTOK + k0 + vpos);
            vpre1 = *(const float4*)(vbase + (size_t)(vch + 32) * NTOK + k0 + vpos);
        }

        // ---- QK: 4 n-tiles x 3xTF32 mma. S col c of tile nt = key 8*nt+c ----
        float d[4][4];
#pragma unroll
        for (int nt = 0; nt < 4; nt++) {
            const float2 kb2 = *(const float2*)&Kb[grp][nt * 8 + g][2 * tig];
            const float2 kd2 = *(const float2*)&Kd[grp][nt * 8 + g][2 * tig];
            const u32 kb0 = __float_as_uint(kb2.x), kb1 = __float_as_uint(kb2.y);
            const u32 kd0 = __float_as_uint(kd2.x), kd1 = __float_as_uint(kd2.y);
            d[nt][0] = 0.0f; d[nt][1] = 0.0f; d[nt][2] = 0.0f; d[nt][3] = 0.0f;
            mma_tf32(d[nt], Qb[0], Qb[1], Qb[2], Qb[3], kb0, kb1);
            mma_tf32(d[nt], Qb[0], Qb[1], Qb[2], Qb[3], kd0, kd1);
            mma_tf32(d[nt], Qd[0], Qd[1], Qd[2], Qd[3], kb0, kb1);
        }

        // ---- exp: D-frag (rows g,g+8; cols 2tig,2tig+1 of tile nt) becomes
        //      the PV A-fragment directly: pa[2*nt+par] = p(rowA, key 8nt+2tig+par)
        u32 pa[8], pb[8];
#pragma unroll
        for (int nt = 0; nt < 4; nt++) {
            const u32 ra0 = tf32_bits(__expf(d[nt][0]));
            const u32 ra1 = tf32_bits(__expf(d[nt][1]));
            const u32 rb0 = tf32_bits(__expf(d[nt][2]));
            const u32 rb1 = tf32_bits(__expf(d[nt][3]));
            pa[2 * nt] = ra0;     la0 += __uint_as_float(ra0);
            pa[2 * nt + 1] = ra1; la1 += __uint_as_float(ra1);
            pb[2 * nt] = rb0;     lb0 += __uint_as_float(rb0);
            pb[2 * nt + 1] = rb1; lb1 += __uint_as_float(rb1);
        }

        // ---- P x V via mma.sync; V positions match psi so frags line up ----
#pragma unroll
        for (int n = 0; n < 8; n++) {
            const float4 vA = *(const float4*)&Vs[grp][n * 8 + g][8 * tig];
            const float4 vB = *(const float4*)&Vs[grp][n * 8 + g][8 * tig + 4];
            mma_tf32(o[n], pa[0], pb[0], pa[1], pb[1],
                     __float_as_uint(vA.x), __float_as_uint(vA.y));
            mma_tf32(o[n], pa[2], pb[2], pa[3], pb[3],
                     __float_as_uint(vA.z), __float_as_uint(vA.w));
            mma_tf32(o[n], pa[4], pb[4], pa[5], pb[5],
                     __float_as_uint(vB.x), __float_as_uint(vB.y));
            mma_tf32(o[n], pa[6], pb[6], pa[7], pb[7],
                     __float_as_uint(vB.z), __float_as_uint(vB.w));
        }

        GBAR(barid);
        if (more) {
            if (lt < 64) {
                ((float4*)Kb[grp])[lt] = kbp;
                ((float4*)Kd[grp])[lt] = kdp;
            }
            *(float4*)&Vs[grp][vch][vpos]      = vpre0;
            *(float4*)&Vs[grp][vch + 32][vpos] = vpre1;
        }
        GBAR(barid);
    }

    float la = la0 + la1;
    float lb = lb0 + lb1;
    la += __shfl_xor_sync(0xffffffffu, la, 1);
    la += __shfl_xor_sync(0xffffffffu, la, 2);
    lb += __shfl_xor_sync(0xffffffffu, lb, 1);
    lb += __shfl_xor_sync(0xffffffffu, lb, 2);

    // ---- merge split-K partials ----
#pragma unroll
    for (int h = 0; h < 2; h++) {
        if (grp == 1) {
            if (h == 0 && tig == 0) {
                lsm[rA_l] = la;
                lsm[rB_l] = lb;
            }
#pragma unroll
            for (int n = h * 4; n < h * 4 + 4; n++) {
                const int col = (n * 8 + 2 * tig) & 31;
                *(float2*)&osm[rA_l][col] = make_float2(o[n][0], o[n][1]);
                *(float2*)&osm[rB_l][col] = make_float2(o[n][2], o[n][3]);
            }
        }
        __syncthreads();
        if (grp == 0) {
            if (h == 0) { la += lsm[rA_l]; lb += lsm[rB_l]; }
#pragma unroll
            for (int n = h * 4; n < h * 4 + 4; n++) {
                const int col = (n * 8 + 2 * tig) & 31;
                const float2 ea = *(const float2*)&osm[rA_l][col];
                const float2 eb = *(const float2*)&osm[rB_l][col];
                o[n][0] += ea.x; o[n][1] += ea.y;
                o[n][2] += eb.x; o[n][3] += eb.y;
            }
        }
        __syncthreads();
    }

    if (grp == 0) {
        const float gamma = *gamma_p;
        const float gia = gamma / la;
        const float gib = gamma / lb;
        const size_t baseA = ((size_t)bid * NTOK + rowA) * CDIM;
        const size_t baseB = ((size_t)bid * NTOK + rowB) * CDIM;
#pragma unroll
        for (int n = 0; n < 8; n++) {
            const int col = n * 8 + 2 * tig;
            const float2 xvA = *(const float2*)&x[baseA + col];
            const float2 xvB = *(const float2*)&x[baseB + col];
            float2 ovA, ovB;
            ovA.x = gia * o[n][0] + xvA.x;
            ovA.y = gia * o[n][1] + xvA.y;
            ovB.x = gib * o[n][2] + xvB.x;
            ovB.y = gib * o[n][3] + xvB.y;
            *(float2*)&out[baseA + col] = ovA;
            *(float2*)&out[baseB + col] = ovB;
        }
    }
}

extern "C" void kernel_launch(void* const* d_in, const int* in_sizes, int n_in,
                              void* d_out, int out_size)
{
    const float* x     = (const float*)d_in[0];
    const float* Wf    = (const float*)d_in[1];
    const float* bf    = (const float*)d_in[2];
    const float* Wg    = (const float*)d_in[3];
    const float* bg    = (const float*)d_in[4];
    const float* Wh    = (const float*)d_in[5];
    const float* bh    = (const float*)d_in[6];
    const float* gamma = (const float*)d_in[7];
    float* out = (float*)d_out;

    proj_kernel<<<(BATCH * NTOK) / 64, 128>>>(x, Wf, bf, Wg, bg, Wh, bh);
    attn_kernel<<<dim3(NTOK / QB, BATCH), 512>>>(x, gamma, out);
}

// round 8
// speedup vs baseline: 2.3857x; 1.5318x over previous
#include <cuda_runtime.h>
#include <cuda_bf16.h>
#include <cstdint>

#define BATCH 4
#define NTOK 4096        // H*W
#define CDIM 64
#define DDIM 8
#define KT 32            // keys per tile
#define NT (NTOK / KT)   // 128 tiles
#define QB 128           // queries per CTA
#define LOG2E 1.4426950408889634f

typedef unsigned int u32;

// group barrier: 256 threads, barrier id 1 or 2
#define GBAR(id) asm volatile("bar.sync %0, %1;" :: "r"(id), "r"(256) : "memory")

__device__ __forceinline__ float ex2f(float x) {
    float r;
    asm("ex2.approx.f32 %0, %1;" : "=f"(r) : "f"(x));
    return r;
}
// pack two f32 -> bf16x2 (hi in upper half, lo in lower half)
__device__ __forceinline__ u32 pack_bf16(float hi, float lo) {
    u32 r;
    asm("cvt.rn.bf16x2.f32 %0, %1, %2;" : "=r"(r) : "f"(hi), "f"(lo));
    return r;
}

// D(16x8,f32) += A(16x16,bf16) * B(16x8,bf16)
__device__ __forceinline__ void mma_bf16(float* d,
                                         u32 a0, u32 a1, u32 a2, u32 a3,
                                         u32 b0, u32 b1) {
    asm("mma.sync.aligned.m16n8k16.row.col.f32.bf16.bf16.f32 "
        "{%0,%1,%2,%3}, {%4,%5,%6,%7}, {%8,%9}, {%0,%1,%2,%3};"
        : "+f"(d[0]), "+f"(d[1]), "+f"(d[2]), "+f"(d[3])
        : "r"(a0), "r"(a1), "r"(a2), "r"(a3), "r"(b0), "r"(b1));
}
// D = A*B + 0 (separate zero C operand; no pre-zeroing of D needed)
__device__ __forceinline__ void mma_bf16_z(float* d,
                                           u32 a0, u32 a1, u32 a2, u32 a3,
                                           u32 b0, u32 b1) {
    asm("mma.sync.aligned.m16n8k16.row.col.f32.bf16.bf16.f32 "
        "{%0,%1,%2,%3}, {%4,%5,%6,%7}, {%8,%9}, {%10,%11,%12,%13};"
        : "=f"(d[0]), "=f"(d[1]), "=f"(d[2]), "=f"(d[3])
        : "r"(a0), "r"(a1), "r"(a2), "r"(a3), "r"(b0), "r"(b1),
          "f"(0.0f), "f"(0.0f), "f"(0.0f), "f"(0.0f));
}

// ---------------- scratch ----------------
__device__ float g_q[BATCH * NTOK * DDIM];            // fp32 q, pre-scaled by log2(e)
// per key: 8 u32 = [kb(0,1), kd(0,1), kb(2,3), kd(2,3), kb(4,5), kd(4,5), kb(6,7), kd(6,7)]
__device__ u32 g_kp[BATCH * NTOK * 8];
// bf16 v, channel-major [B][C][NTOK], key order permuted within each 32-block (see p() below)
__device__ __nv_bfloat16 g_vb[(size_t)BATCH * CDIM * NTOK];

// position of key j (0..31) within its 32-block in g_vb / Vs
__device__ __forceinline__ int vperm(int j) {
    const int blk = j >> 4;
    const int k   = j & 15;
    const int rho = 4 * ((k >> 1) & 3) + (k & 1) + 2 * (k >> 3);
    return (rho >> 2) * 8 + blk * 4 + (rho & 3);
}

// ---------------------------------------------------------------------------
// Projection. 128 threads, 64 rows/CTA (2 threads per row: channel halves).
// ---------------------------------------------------------------------------
__global__ __launch_bounds__(128) void proj_kernel(
    const float* __restrict__ x,
    const float* __restrict__ Wf, const float* __restrict__ bf,
    const float* __restrict__ Wg, const float* __restrict__ bg,
    const float* __restrict__ Wh, const float* __restrict__ bh)
{
    __shared__ __align__(16) float xs[64][68];
    __shared__ __align__(16) float WhT[64][68];
    __shared__ __align__(16) float WfT[8][68];
    __shared__ __align__(16) float WgT[8][68];
    __shared__ float bias[64];

    const int tid = threadIdx.x;
    const int rowbase = blockIdx.x * 64;

    for (int i = tid; i < 1024; i += 128) {
        const int r = i >> 4, c4 = i & 15;
        *(float4*)&xs[r][c4 * 4] = ((const float4*)(x + (size_t)rowbase * CDIM))[i];
    }
    for (int i = tid; i < 4096; i += 128)
        WhT[i & 63][i >> 6] = Wh[i];
    for (int i = tid; i < 512; i += 128) {
        WfT[i & 7][i >> 3] = Wf[i];
        WgT[i & 7][i >> 3] = Wg[i];
    }
    if (tid < 64) bias[tid] = bh[tid];
    __syncthreads();

    const int rloc = (tid & 31) | ((tid >> 6) << 5);   // 0..63
    const int half = (tid >> 5) & 1;
    const int row  = rowbase + rloc;
    const int b    = row >> 12;
    const int nl   = row & (NTOK - 1);
    const int key  = nl & 31;
    const int nlp  = (nl & ~31) | vperm(key);

    float xr[64];
#pragma unroll
    for (int c4 = 0; c4 < 16; c4++) {
        const float4 t = *(const float4*)&xs[rloc][c4 * 4];
        xr[c4 * 4 + 0] = t.x; xr[c4 * 4 + 1] = t.y;
        xr[c4 * 4 + 2] = t.z; xr[c4 * 4 + 3] = t.w;
    }

    // v: my 32-channel half, bf16, channel-major, key-permuted
#pragma unroll 1
    for (int ch = half * 32; ch < half * 32 + 32; ch++) {
        float a = bias[ch];
        const float4* w = (const float4*)&WhT[ch][0];
#pragma unroll
        for (int c4 = 0; c4 < 16; c4++) {
            const float4 ww = w[c4];
            a += xr[c4 * 4 + 0] * ww.x;
            a += xr[c4 * 4 + 1] * ww.y;
            a += xr[c4 * 4 + 2] * ww.z;
            a += xr[c4 * 4 + 3] * ww.w;
        }
        g_vb[((size_t)b * CDIM + ch) * NTOK + nlp] = __float2bfloat16_rn(a);
    }

    if (half == 0) {
        // q scaled by log2(e), fp32
        float q8[8];
#pragma unroll
        for (int ch = 0; ch < DDIM; ch++) {
            float a = __ldg(&bf[ch]);
            const float4* w = (const float4*)&WfT[ch][0];
#pragma unroll
            for (int c4 = 0; c4 < 16; c4++) {
                const float4 ww = w[c4];
                a += xr[c4 * 4 + 0] * ww.x;
                a += xr[c4 * 4 + 1] * ww.y;
                a += xr[c4 * 4 + 2] * ww.z;
                a += xr[c4 * 4 + 3] * ww.w;
            }
            q8[ch] = LOG2E * a;
        }
        float* qdst = g_q + (size_t)row * DDIM;
        *(float4*)qdst       = make_float4(q8[0], q8[1], q8[2], q8[3]);
        *(float4*)(qdst + 4) = make_float4(q8[4], q8[5], q8[6], q8[7]);
    } else {
        // k: bf16 split big+residual, packed per key
        float k8[8];
#pragma unroll
        for (int ch = 0; ch < DDIM; ch++) {
            float a = __ldg(&bg[ch]);
            const float4* w = (const float4*)&WgT[ch][0];
#pragma unroll
            for (int c4 = 0; c4 < 16; c4++) {
                const float4 ww = w[c4];
                a += xr[c4 * 4 + 0] * ww.x;
                a += xr[c4 * 4 + 1] * ww.y;
                a += xr[c4 * 4 + 2] * ww.z;
                a += xr[c4 * 4 + 3] * ww.w;
            }
            k8[ch] = a;
        }
        u32 kw[8];
#pragma unroll
        for (int t = 0; t < 4; t++) {
            const float b0 = __bfloat162float(__float2bfloat16_rn(k8[2 * t]));
            const float b1 = __bfloat162float(__float2bfloat16_rn(k8[2 * t + 1]));
            kw[2 * t]     = pack_bf16(b1, b0);
            kw[2 * t + 1] = pack_bf16(k8[2 * t + 1] - b1, k8[2 * t] - b0);
        }
        uint4* kd = (uint4*)&g_kp[(size_t)row * 8];
        kd[0] = make_uint4(kw[0], kw[1], kw[2], kw[3]);
        kd[1] = make_uint4(kw[4], kw[5], kw[6], kw[7]);
    }
}

// ---------------------------------------------------------------------------
// Attention: QK via 2x bf16-split m16n8k16 mma (exact to ~2^-17), ex2 into
// PV A-fragments (bf16x2 packs), PV via bf16 m16n8k16. 512 threads = 2
// split-K groups of 256 (named barriers); o/l linear; merge at end.
// ---------------------------------------------------------------------------
__global__ __launch_bounds__(512, 1) void attn_kernel(
    const float* __restrict__ x,
    const float* __restrict__ gamma_p,
    float* __restrict__ out)
{
    __shared__ __align__(16) u32 Kc[2][KT * 8];       // 2 x 1 KB
    __shared__ __align__(16) u32 Vs[2][CDIM * 16];    // 2 x 4 KB (bf16 pairs)
    __shared__ __align__(16) float osm[QB][34];       // 17 KB
    __shared__ float lsm[QB];

    const int tid  = threadIdx.x;
    const int grp  = tid >> 8;
    const int lt   = tid & 255;
    const int warp = lt >> 5;
    const int lane = tid & 31;
    const int g    = lane >> 2;
    const int t4   = lane & 3;
    const int bid  = blockIdx.y;
    const int q0   = blockIdx.x * QB;
    const int barid = grp + 1;

    const int rA_l = warp * 16 + g;
    const int rB_l = rA_l + 8;
    const int rowA = q0 + rA_l;
    const int rowB = q0 + rB_l;

    // QK A-frags: a0 = Qb(rowA, dims 2t,2t+1), a1 = Qb(rowB), a2 = Qd(rowA), a3 = Qd(rowB)
    u32 QA0, QA1, QA2, QA3;
    {
        const float2 qA = *(const float2*)(g_q + ((size_t)bid * NTOK + rowA) * DDIM + 2 * t4);
        const float2 qB = *(const float2*)(g_q + ((size_t)bid * NTOK + rowB) * DDIM + 2 * t4);
        const float bAx = __bfloat162float(__float2bfloat16_rn(qA.x));
        const float bAy = __bfloat162float(__float2bfloat16_rn(qA.y));
        const float bBx = __bfloat162float(__float2bfloat16_rn(qB.x));
        const float bBy = __bfloat162float(__float2bfloat16_rn(qB.y));
        QA0 = pack_bf16(bAy, bAx);
        QA1 = pack_bf16(bBy, bBx);
        QA2 = pack_bf16(qA.y - bAy, qA.x - bAx);
        QA3 = pack_bf16(qB.y - bBy, qB.x - bBx);
    }

    float o[8][4];
#pragma unroll
    for (int n = 0; n < 8; n++)
#pragma unroll
        for (int r = 0; r < 4; r++) o[n][r] = 0.0f;
    float la0 = 0.0f, la1 = 0.0f, lb0 = 0.0f, lb1 = 0.0f;

    const u32* kpbase = g_kp + (size_t)bid * NTOK * 8;
    const __nv_bfloat16* vbbase = g_vb + (size_t)bid * CDIM * NTOK;

    const int t0 = grp * (NT / 2);
    const int t1 = t0 + (NT / 2);

    uint4 kpre, vpre;
    const int vch   = lt >> 2;        // 0..63
    const int vchk  = lt & 3;         // 16B chunk

    {
        const int k0 = t0 * KT;
        if (lt < 64) kpre = ((const uint4*)(kpbase + (size_t)k0 * 8))[lt];
        vpre = *(const uint4*)((const char*)(vbbase + (size_t)vch * NTOK + k0) + vchk * 16);
        if (lt < 64) ((uint4*)Kc[grp])[lt] = kpre;
        ((uint4*)Vs[grp])[lt] = vpre;
    }
    GBAR(barid);

    for (int t = t0; t < t1; t++) {
        const bool more = (t + 1 < t1);
        if (more) {
            const int k0 = (t + 1) * KT;
            if (lt < 64) kpre = ((const uint4*)(kpbase + (size_t)k0 * 8))[lt];
            vpre = *(const uint4*)((const char*)(vbbase + (size_t)vch * NTOK + k0) + vchk * 16);
        }

        // ---- QK: 4 n-tiles x 2 bf16-split mmas; s' = log2e * q.k (exact) ----
        float d[4][4];
#pragma unroll
        for (int nt = 0; nt < 4; nt++) {
            const uint2 kk = *(const uint2*)&Kc[grp][(nt * 8 + g) * 8 + t4 * 2];
            mma_bf16_z(d[nt], QA0, QA1, QA2, QA3, kk.x, kk.y);  // Qb.kb + Qd.kd
            mma_bf16 (d[nt], QA0, QA1, QA2, QA3, kk.y, kk.x);   // Qb.kd + Qd.kb
        }

        // ---- exp2 + l + pack into PV A-frags (bf16x2) ----
        u32 pf[2][4];
#pragma unroll
        for (int s = 0; s < 2; s++) {
            const float eA0 = ex2f(d[2 * s][0]),     eA1 = ex2f(d[2 * s][1]);
            const float eB0 = ex2f(d[2 * s][2]),     eB1 = ex2f(d[2 * s][3]);
            const float fA0 = ex2f(d[2 * s + 1][0]), fA1 = ex2f(d[2 * s + 1][1]);
            const float fB0 = ex2f(d[2 * s + 1][2]), fB1 = ex2f(d[2 * s + 1][3]);
            la0 += eA0 + eA1;  la1 += fA0 + fA1;
            lb0 += eB0 + eB1;  lb1 += fB0 + fB1;
            pf[s][0] = pack_bf16(eA1, eA0);   // rowA, keys lo
            pf[s][1] = pack_bf16(eB1, eB0);   // rowB, keys lo
            pf[s][2] = pack_bf16(fA1, fA0);   // rowA, keys hi
            pf[s][3] = pack_bf16(fB1, fB0);   // rowB, keys hi
        }

        // ---- P x V: 8 n-tiles x 2 k-steps, B-frags one LDS.128 per n ----
#pragma unroll
        for (int n = 0; n < 8; n++) {
            const uint4 vv = *(const uint4*)&Vs[grp][(n * 8 + g) * 16 + t4 * 4];
            mma_bf16(o[n], pf[0][0], pf[0][1], pf[0][2], pf[0][3], vv.x, vv.y);
            mma_bf16(o[n], pf[1][0], pf[1][1], pf[1][2], pf[1][3], vv.z, vv.w);
        }

        GBAR(barid);
        if (more) {
            if (lt < 64) ((uint4*)Kc[grp])[lt] = kpre;
            ((uint4*)Vs[grp])[lt] = vpre;
        }
        GBAR(barid);
    }

    float la = la0 + la1;
    float lb = lb0 + lb1;
    la += __shfl_xor_sync(0xffffffffu, la, 1);
    la += __shfl_xor_sync(0xffffffffu, la, 2);
    lb += __shfl_xor_sync(0xffffffffu, lb, 1);
    lb += __shfl_xor_sync(0xffffffffu, lb, 2);

    // ---- merge split-K partials ----
#pragma unroll
    for (int h = 0; h < 2; h++) {
        if (grp == 1) {
            if (h == 0 && t4 == 0) {
                lsm[rA_l] = la;
                lsm[rB_l] = lb;
            }
#pragma unroll
            for (int n = h * 4; n < h * 4 + 4; n++) {
                const int col = (n * 8 + 2 * t4) & 31;
                *(float2*)&osm[rA_l][col] = make_float2(o[n][0], o[n][1]);
                *(float2*)&osm[rB_l][col] = make_float2(o[n][2], o[n][3]);
            }
        }
        __syncthreads();
        if (grp == 0) {
            if (h == 0) { la += lsm[rA_l]; lb += lsm[rB_l]; }
#pragma unroll
            for (int n = h * 4; n < h * 4 + 4; n++) {
                const int col = (n * 8 + 2 * t4) & 31;
                const float2 ea = *(const float2*)&osm[rA_l][col];
                const float2 eb = *(const float2*)&osm[rB_l][col];
                o[n][0] += ea.x; o[n][1] += ea.y;
                o[n][2] += eb.x; o[n][3] += eb.y;
            }
        }
        __syncthreads();
    }

    if (grp == 0) {
        const float gamma = *gamma_p;
        const float gia = gamma / la;
        const float gib = gamma / lb;
        const size_t baseA = ((size_t)bid * NTOK + rowA) * CDIM;
        const size_t baseB = ((size_t)bid * NTOK + rowB) * CDIM;
#pragma unroll
        for (int n = 0; n < 8; n++) {
            const int col = n * 8 + 2 * t4;
            const float2 xvA = *(const float2*)&x[baseA + col];
            const float2 xvB = *(const float2*)&x[baseB + col];
            float2 ovA, ovB;
            ovA.x = gia * o[n][0] + xvA.x;
            ovA.y = gia * o[n][1] + xvA.y;
            ovB.x = gib * o[n][2] + xvB.x;
            ovB.y = gib * o[n][3] + xvB.y;
            *(float2*)&out[baseA + col] = ovA;
            *(float2*)&out[baseB + col] = ovB;
        }
    }
}

extern "C" void kernel_launch(void* const* d_in, const int* in_sizes, int n_in,
                              void* d_out, int out_size)
{
    const float* x     = (const float*)d_in[0];
    const float* Wf    = (const float*)d_in[1];
    const float* bf    = (const float*)d_in[2];
    const float* Wg    = (const float*)d_in[3];
    const float* bg    = (const float*)d_in[4];
    const float* Wh    = (const float*)d_in[5];
    const float* bh    = (const float*)d_in[6];
    const float* gamma = (const float*)d_in[7];
    float* out = (float*)d_out;

    proj_kernel<<<(BATCH * NTOK) / 64, 128>>>(x, Wf, bf, Wg, bg, Wh, bh);
    attn_kernel<<<dim3(NTOK / QB, BATCH), 512>>>(x, gamma, out);
}